// round 2
// baseline (speedup 1.0000x reference)
#include <cuda_runtime.h>
#include <math.h>

// Problem constants (shapes fixed by the dataset; derived from in_sizes at launch)
#define BMAX 8192
#define TILE 128
#define KC   32
#define NTMAX (BMAX / TILE)                      // 64
#define NPAIR_MAX (NTMAX * (NTMAX + 1) / 2)      // 2080
#define NBLK8_MAX (BMAX / 8)                     // 1024

__device__ float g_sq[BMAX];
__device__ float g_pair_partial[NPAIR_MAX];
__device__ float g_ce_partial[NBLK8_MAX];
__device__ float g_qua_partial[NBLK8_MAX];

// ---------------------------------------------------------------------------
// Kernel 1: per-row squared norms of Fi + quantization-BCE partial sums.
// One warp per row (BITS=64 -> 2 elements/lane).
// ---------------------------------------------------------------------------
__global__ void prep_kernel(const float* __restrict__ Fi, int B, int BITS) {
    int gwarp = (blockIdx.x * blockDim.x + threadIdx.x) >> 5;
    int lane  = threadIdx.x & 31;
    int wib   = threadIdx.x >> 5;

    float sq = 0.f, qua = 0.f;
    if (gwarp < B) {
        const float* row = Fi + (size_t)gwarp * BITS;
        for (int c = lane; c < BITS; c += 32) {
            float p  = row[c];
            sq += p * p;
            float lp = fmaxf(logf(p), -100.f);
            float l1 = fmaxf(log1pf(-p), -100.f);
            qua += -(p * lp + (1.f - p) * l1);
        }
        #pragma unroll
        for (int o = 16; o; o >>= 1) {
            sq  += __shfl_down_sync(0xFFFFFFFFu, sq,  o);
            qua += __shfl_down_sync(0xFFFFFFFFu, qua, o);
        }
        if (lane == 0) g_sq[gwarp] = sq;
    }
    __shared__ float s[8];
    if (lane == 0) s[wib] = qua;  // qua==0 for warps with gwarp>=B
    __syncthreads();
    if (threadIdx.x == 0) {
        float t = 0.f;
        #pragma unroll
        for (int i = 0; i < 8; i++) t += s[i];
        g_qua_partial[blockIdx.x] = t;
    }
}

// ---------------------------------------------------------------------------
// Kernel 2: cross-entropy for Yi and Ym (both weight 1.0). One warp per row.
// ---------------------------------------------------------------------------
__global__ void ce_kernel(const float* __restrict__ Yi, const float* __restrict__ Ym,
                          const int* __restrict__ y, int B, int C) {
    int gwarp = (blockIdx.x * blockDim.x + threadIdx.x) >> 5;
    int lane  = threadIdx.x & 31;
    int wib   = threadIdx.x >> 5;

    float loss = 0.f;
    if (gwarp < B) {
        int label = y[gwarp];
        #pragma unroll
        for (int m = 0; m < 2; m++) {
            const float* row = (m ? Ym : Yi) + (size_t)gwarp * C;
            float mx = -INFINITY;
            for (int c = lane; c < C; c += 32) mx = fmaxf(mx, row[c]);
            #pragma unroll
            for (int o = 16; o; o >>= 1) mx = fmaxf(mx, __shfl_xor_sync(0xFFFFFFFFu, mx, o));
            float se = 0.f;
            for (int c = lane; c < C; c += 32) se += expf(row[c] - mx);
            #pragma unroll
            for (int o = 16; o; o >>= 1) se += __shfl_xor_sync(0xFFFFFFFFu, se, o);
            float xl = row[label];  // broadcast load
            loss += logf(se) + mx - xl;
        }
    }
    __shared__ float s[8];
    if (lane == 0) s[wib] = loss;
    __syncthreads();
    if (threadIdx.x == 0) {
        float t = 0.f;
        #pragma unroll
        for (int i = 0; i < 8; i++) t += s[i];
        g_ce_partial[blockIdx.x] = t;
    }
}

// ---------------------------------------------------------------------------
// Kernel 3: pairwise contrastive term. Upper-triangular 128x128 tiles of the
// Gram matrix, fused epilogue + block reduction (Gram never materialized).
// 256 threads, each computes an 8x8 register micro-tile.
// ---------------------------------------------------------------------------
__global__ void __launch_bounds__(256, 2)
pair_kernel(const float* __restrict__ Fi, const int* __restrict__ y,
            int B, int BITS, int NT) {
    __shared__ float As[KC][TILE];
    __shared__ float Bs[KC][TILE];
    __shared__ float sqI[TILE], sqJ[TILE];
    __shared__ int   yI[TILE],  yJ[TILE];
    __shared__ float red[256];

    // linear block -> (bi, bj) with bi <= bj
    int t = blockIdx.x;
    int bi = 0, rowlen = NT;
    while (t >= rowlen) { t -= rowlen; bi++; rowlen--; }
    int bj = bi + t;
    int i0 = bi * TILE, j0 = bj * TILE;

    int tid = threadIdx.x;
    int tx = tid & 15, ty = tid >> 4;

    if (tid < TILE) { sqI[tid] = g_sq[i0 + tid]; yI[tid] = y[i0 + tid]; }
    else            { int u = tid - TILE; sqJ[u] = g_sq[j0 + u]; yJ[u] = y[j0 + u]; }

    float acc[8][8];
    #pragma unroll
    for (int i = 0; i < 8; i++)
        #pragma unroll
        for (int j = 0; j < 8; j++) acc[i][j] = 0.f;

    for (int kc = 0; kc < BITS; kc += KC) {
        __syncthreads();
        // load 128 x KC chunk of each tile, transposed into smem (k-major)
        #pragma unroll
        for (int p = 0; p < 4; p++) {
            int r  = p * 32 + (tid >> 3);
            int c4 = (tid & 7) * 4;
            float4 a = *(const float4*)(Fi + (size_t)(i0 + r) * BITS + kc + c4);
            As[c4 + 0][r] = a.x; As[c4 + 1][r] = a.y;
            As[c4 + 2][r] = a.z; As[c4 + 3][r] = a.w;
            float4 b = *(const float4*)(Fi + (size_t)(j0 + r) * BITS + kc + c4);
            Bs[c4 + 0][r] = b.x; Bs[c4 + 1][r] = b.y;
            Bs[c4 + 2][r] = b.z; Bs[c4 + 3][r] = b.w;
        }
        __syncthreads();
        #pragma unroll
        for (int k = 0; k < KC; k++) {
            float a[8], b[8];
            *(float4*)(a)     = *(const float4*)&As[k][ty * 8];
            *(float4*)(a + 4) = *(const float4*)&As[k][ty * 8 + 4];
            *(float4*)(b)     = *(const float4*)&Bs[k][tx * 8];
            *(float4*)(b + 4) = *(const float4*)&Bs[k][tx * 8 + 4];
            #pragma unroll
            for (int i = 0; i < 8; i++)
                #pragma unroll
                for (int j = 0; j < 8; j++)
                    acc[i][j] = fmaf(a[i], b[j], acc[i][j]);
        }
    }

    // fused epilogue: D = sq_i + sq_j - 2*g ; same ? D : relu(32 - D); i<j only
    float local = 0.f;
    bool diag = (bi == bj);
    #pragma unroll
    for (int i = 0; i < 8; i++) {
        int li = ty * 8 + i;
        float si = sqI[li];
        int   yi = yI[li];
        #pragma unroll
        for (int j = 0; j < 8; j++) {
            int lj = tx * 8 + j;
            float D = si + sqJ[lj] - 2.f * acc[i][j];
            D = fmaxf(D, 0.f);
            float v = (yi == yJ[lj]) ? D : fmaxf(32.f - D, 0.f);
            if (!diag || (i0 + li) < (j0 + lj)) local += v;
        }
    }

    red[tid] = local;
    __syncthreads();
    #pragma unroll
    for (int s = 128; s; s >>= 1) {
        if (tid < s) red[tid] += red[tid + s];
        __syncthreads();
    }
    if (tid == 0) g_pair_partial[blockIdx.x] = red[0];
}

// ---------------------------------------------------------------------------
// Kernel 4: combine all partials (fixed order, double accum -> deterministic)
// ---------------------------------------------------------------------------
__global__ void final_kernel(float* __restrict__ out, int B, int BITS,
                             int npair, int nce, int nqua) {
    __shared__ double s[256];
    int tid = threadIdx.x;
    double pair = 0.0, ce = 0.0, qua = 0.0;
    for (int i = tid; i < npair; i += 256) pair += (double)g_pair_partial[i];
    for (int i = tid; i < nce;   i += 256) ce   += (double)g_ce_partial[i];
    for (int i = tid; i < nqua;  i += 256) qua  += (double)g_qua_partial[i];

    double invPair = 1.0 / (2.0 * (double)B * (double)(B - 1));
    double invB    = 1.0 / (double)B;
    double sclQ    = 0.1 / ((double)B * (double)BITS);   // EPSILUO = 0.1
    s[tid] = pair * invPair + ce * invB + qua * sclQ;
    __syncthreads();
    #pragma unroll
    for (int o = 128; o; o >>= 1) {
        if (tid < o) s[tid] += s[tid + o];
        __syncthreads();
    }
    if (tid == 0) out[0] = (float)s[0];
}

// ---------------------------------------------------------------------------
extern "C" void kernel_launch(void* const* d_in, const int* in_sizes, int n_in,
                              void* d_out, int out_size) {
    const float* Ym = (const float*)d_in[0];
    const float* Fi = (const float*)d_in[1];
    const float* Yi = (const float*)d_in[2];
    const int*   y  = (const int*)  d_in[3];

    int B    = in_sizes[3];
    int C    = in_sizes[0] / B;
    int BITS = in_sizes[1] / B;

    int nblk8 = (B + 7) / 8;          // 8 warps/block, one row each
    int NT    = B / TILE;
    int npair = NT * (NT + 1) / 2;

    prep_kernel<<<nblk8, 256>>>(Fi, B, BITS);
    ce_kernel<<<nblk8, 256>>>(Yi, Ym, y, B, C);
    pair_kernel<<<npair, 256>>>(Fi, y, B, BITS, NT);
    final_kernel<<<1, 256>>>((float*)d_out, B, BITS, npair, nblk8, nblk8);
}

// round 4
// speedup vs baseline: 2.1310x; 2.1310x over previous
#include <cuda_runtime.h>
#include <math.h>

#define BMAX 8192
#define TILE 128
#define NTMAX (BMAX / TILE)                      // 64
#define NPAIR_MAX (NTMAX * (NTMAX + 1) / 2)      // 2080
#define NBLK8_MAX (BMAX / 8)                     // 1024
#define SMS 68                                   // smem row stride (floats), conflict-free

__device__ float g_sq[BMAX];
__device__ float g_pair_partial[NPAIR_MAX];
__device__ float g_ce_partial[NBLK8_MAX];
__device__ float g_qua_partial[NBLK8_MAX];

// ---------------------------------------------------------------------------
// Kernel 1: per-row squared norms of Fi + quantization-BCE partial sums.
// ---------------------------------------------------------------------------
__global__ void prep_kernel(const float* __restrict__ Fi, int B, int BITS) {
    int gwarp = (blockIdx.x * blockDim.x + threadIdx.x) >> 5;
    int lane  = threadIdx.x & 31;
    int wib   = threadIdx.x >> 5;

    float sq = 0.f, qua = 0.f;
    if (gwarp < B) {
        const float* row = Fi + (size_t)gwarp * BITS;
        for (int c = lane; c < BITS; c += 32) {
            float p  = row[c];
            sq += p * p;
            float lp = fmaxf(logf(p), -100.f);
            float l1 = fmaxf(log1pf(-p), -100.f);
            qua += -(p * lp + (1.f - p) * l1);
        }
        #pragma unroll
        for (int o = 16; o; o >>= 1) {
            sq  += __shfl_down_sync(0xFFFFFFFFu, sq,  o);
            qua += __shfl_down_sync(0xFFFFFFFFu, qua, o);
        }
        if (lane == 0) g_sq[gwarp] = sq;
    }
    __shared__ float s[8];
    if (lane == 0) s[wib] = qua;
    __syncthreads();
    if (threadIdx.x == 0) {
        float t = 0.f;
        #pragma unroll
        for (int i = 0; i < 8; i++) t += s[i];
        g_qua_partial[blockIdx.x] = t;
    }
}

// ---------------------------------------------------------------------------
// Kernel 2: cross-entropy for Yi and Ym. One warp per row.
// ---------------------------------------------------------------------------
__global__ void ce_kernel(const float* __restrict__ Yi, const float* __restrict__ Ym,
                          const int* __restrict__ y, int B, int C) {
    int gwarp = (blockIdx.x * blockDim.x + threadIdx.x) >> 5;
    int lane  = threadIdx.x & 31;
    int wib   = threadIdx.x >> 5;

    float loss = 0.f;
    if (gwarp < B) {
        int label = y[gwarp];
        #pragma unroll
        for (int m = 0; m < 2; m++) {
            const float* row = (m ? Ym : Yi) + (size_t)gwarp * C;
            float mx = -INFINITY;
            for (int c = lane; c < C; c += 32) mx = fmaxf(mx, row[c]);
            #pragma unroll
            for (int o = 16; o; o >>= 1) mx = fmaxf(mx, __shfl_xor_sync(0xFFFFFFFFu, mx, o));
            float se = 0.f;
            for (int c = lane; c < C; c += 32) se += expf(row[c] - mx);
            #pragma unroll
            for (int o = 16; o; o >>= 1) se += __shfl_xor_sync(0xFFFFFFFFu, se, o);
            float xl = row[label];
            loss += logf(se) + mx - xl;
        }
    }
    __shared__ float s[8];
    if (lane == 0) s[wib] = loss;
    __syncthreads();
    if (threadIdx.x == 0) {
        float t = 0.f;
        #pragma unroll
        for (int i = 0; i < 8; i++) t += s[i];
        g_ce_partial[blockIdx.x] = t;
    }
}

// ---------------------------------------------------------------------------
// Kernel 3: pairwise term via tf32 tensor-core MMA, fused epilogue.
// Block tile 128x128, K=64 fully resident. 8 warps, warp tile 64(M)x32(N).
// Accumulators live in registers (mma.sync), so the epilogue is free of any
// TMEM/SMEM roundtrip for D.
// ---------------------------------------------------------------------------
__device__ __forceinline__ unsigned f2tf32(float x) {
    unsigned u;
    asm("cvt.rna.tf32.f32 %0, %1;" : "=r"(u) : "f"(x));
    return u;
}

__device__ __forceinline__ void mma_tf32(float* c, const unsigned* a, const unsigned* b) {
    asm volatile(
        "mma.sync.aligned.m16n8k8.row.col.f32.tf32.tf32.f32 "
        "{%0,%1,%2,%3}, {%4,%5,%6,%7}, {%8,%9}, {%0,%1,%2,%3};\n"
        : "+f"(c[0]), "+f"(c[1]), "+f"(c[2]), "+f"(c[3])
        : "r"(a[0]), "r"(a[1]), "r"(a[2]), "r"(a[3]), "r"(b[0]), "r"(b[1]));
}

extern __shared__ unsigned dyn_smem[];   // As[128][SMS], Bs[128][SMS] (tf32 bits)

__global__ void __launch_bounds__(256, 2)
pair_mma_kernel(const float* __restrict__ Fi, const int* __restrict__ y,
                int B, int NT) {
    unsigned* As = dyn_smem;                 // 128*SMS
    unsigned* Bs = dyn_smem + TILE * SMS;    // 128*SMS

    __shared__ float sqI[TILE], sqJ[TILE];
    __shared__ int   yI[TILE],  yJ[TILE];
    __shared__ float red[256];

    // linear block -> (bi, bj) with bi <= bj
    int t = blockIdx.x;
    int bi = 0, rowlen = NT;
    while (t >= rowlen) { t -= rowlen; bi++; rowlen--; }
    int bj = bi + t;
    int i0 = bi * TILE, j0 = bj * TILE;

    int tid  = threadIdx.x;
    int lane = tid & 31;
    int wid  = tid >> 5;
    int g    = lane >> 2;      // group id (0..7)
    int tg   = lane & 3;       // thread in group (0..3)
    int warpM = (wid >> 2) * 64;   // 0 or 64
    int warpN = (wid & 3) * 32;    // 0,32,64,96

    if (tid < TILE) { sqI[tid] = g_sq[i0 + tid]; yI[tid] = y[i0 + tid]; }
    else            { int u = tid - TILE; sqJ[u] = g_sq[j0 + u]; yJ[u] = y[j0 + u]; }

    // Load + convert both tiles (128 rows x 64 cols each), float4 reads.
    #pragma unroll
    for (int q = tid; q < TILE * 16; q += 256) {
        int row = q >> 4, quad = (q & 15) * 4;
        float4 a = *(const float4*)(Fi + (size_t)(i0 + row) * 64 + quad);
        unsigned* d = As + row * SMS + quad;
        d[0] = f2tf32(a.x); d[1] = f2tf32(a.y); d[2] = f2tf32(a.z); d[3] = f2tf32(a.w);
        float4 b = *(const float4*)(Fi + (size_t)(j0 + row) * 64 + quad);
        unsigned* e = Bs + row * SMS + quad;
        e[0] = f2tf32(b.x); e[1] = f2tf32(b.y); e[2] = f2tf32(b.z); e[3] = f2tf32(b.w);
    }
    __syncthreads();

    float acc[4][4][4];
    #pragma unroll
    for (int mf = 0; mf < 4; mf++)
        #pragma unroll
        for (int nf = 0; nf < 4; nf++)
            #pragma unroll
            for (int c = 0; c < 4; c++) acc[mf][nf][c] = 0.f;

    #pragma unroll
    for (int k0 = 0; k0 < 64; k0 += 8) {
        unsigned a[4][4], b[4][2];
        #pragma unroll
        for (int mf = 0; mf < 4; mf++) {
            const unsigned* base = As + (warpM + mf * 16 + g) * SMS + k0 + tg;
            a[mf][0] = base[0];
            a[mf][1] = base[8 * SMS];
            a[mf][2] = base[4];
            a[mf][3] = base[8 * SMS + 4];
        }
        #pragma unroll
        for (int nf = 0; nf < 4; nf++) {
            const unsigned* base = Bs + (warpN + nf * 8 + g) * SMS + k0 + tg;
            b[nf][0] = base[0];
            b[nf][1] = base[4];
        }
        #pragma unroll
        for (int mf = 0; mf < 4; mf++)
            #pragma unroll
            for (int nf = 0; nf < 4; nf++)
                mma_tf32(acc[mf][nf], a[mf], b[nf]);
    }

    // Fused epilogue: D = sq_i + sq_j - 2*g ; same ? max(D,0) : max(32-D, 0)
    float local = 0.f;
    bool diag = (bi == bj);
    #pragma unroll
    for (int mf = 0; mf < 4; mf++) {
        int r0 = warpM + mf * 16 + g;
        int r1 = r0 + 8;
        float s0 = sqI[r0], s1 = sqI[r1];
        int   q0 = yI[r0],  q1 = yI[r1];
        #pragma unroll
        for (int nf = 0; nf < 4; nf++) {
            int c0 = warpN + nf * 8 + 2 * tg;
            int c1 = c0 + 1;
            float t0 = sqJ[c0], t1 = sqJ[c1];
            int   z0 = yJ[c0],  z1 = yJ[c1];
            const float* A = acc[mf][nf];

            float D00 = fmaxf(s0 + t0 - 2.f * A[0], 0.f);
            float D01 = fmaxf(s0 + t1 - 2.f * A[1], 0.f);
            float D10 = fmaxf(s1 + t0 - 2.f * A[2], 0.f);
            float D11 = fmaxf(s1 + t1 - 2.f * A[3], 0.f);
            float v00 = (q0 == z0) ? D00 : fmaxf(32.f - D00, 0.f);
            float v01 = (q0 == z1) ? D01 : fmaxf(32.f - D01, 0.f);
            float v10 = (q1 == z0) ? D10 : fmaxf(32.f - D10, 0.f);
            float v11 = (q1 == z1) ? D11 : fmaxf(32.f - D11, 0.f);
            if (diag) {
                if (r0 >= c0) v00 = 0.f;
                if (r0 >= c1) v01 = 0.f;
                if (r1 >= c0) v10 = 0.f;
                if (r1 >= c1) v11 = 0.f;
            }
            local += (v00 + v01) + (v10 + v11);
        }
    }

    // block reduce (deterministic)
    #pragma unroll
    for (int o = 16; o; o >>= 1) local += __shfl_down_sync(0xFFFFFFFFu, local, o);
    if (lane == 0) red[wid] = local;
    __syncthreads();
    if (tid == 0) {
        float s = 0.f;
        #pragma unroll
        for (int w = 0; w < 8; w++) s += red[w];
        g_pair_partial[blockIdx.x] = s;
    }
}

// ---------------------------------------------------------------------------
// Kernel 4: combine all partials (fixed order, double accum -> deterministic)
// ---------------------------------------------------------------------------
__global__ void final_kernel(float* __restrict__ out, int B, int BITS,
                             int npair, int nce, int nqua) {
    __shared__ double s[32];
    int tid = threadIdx.x;
    int lane = tid & 31, wid = tid >> 5;

    double pair = 0.0, ce = 0.0, qua = 0.0;
    for (int i = tid; i < npair; i += 1024) pair += (double)g_pair_partial[i];
    for (int i = tid; i < nce;   i += 1024) ce   += (double)g_ce_partial[i];
    for (int i = tid; i < nqua;  i += 1024) qua  += (double)g_qua_partial[i];

    double invPair = 1.0 / (2.0 * (double)B * (double)(B - 1));
    double invB    = 1.0 / (double)B;
    double sclQ    = 0.1 / ((double)B * (double)BITS);
    double v = pair * invPair + ce * invB + qua * sclQ;

    #pragma unroll
    for (int o = 16; o; o >>= 1) v += __shfl_down_sync(0xFFFFFFFFu, v, o);
    if (lane == 0) s[wid] = v;
    __syncthreads();
    if (wid == 0) {
        double t = (lane < 32) ? s[lane] : 0.0;
        #pragma unroll
        for (int o = 16; o; o >>= 1) t += __shfl_down_sync(0xFFFFFFFFu, t, o);
        if (lane == 0) out[0] = (float)t;
    }
}

// ---------------------------------------------------------------------------
extern "C" void kernel_launch(void* const* d_in, const int* in_sizes, int n_in,
                              void* d_out, int out_size) {
    const float* Ym = (const float*)d_in[0];
    const float* Fi = (const float*)d_in[1];
    const float* Yi = (const float*)d_in[2];
    const int*   y  = (const int*)  d_in[3];

    int B    = in_sizes[3];
    int C    = in_sizes[0] / B;
    int BITS = in_sizes[1] / B;

    int nblk8 = (B + 7) / 8;
    int NT    = B / TILE;
    int npair = NT * (NT + 1) / 2;

    static int smem_set = -1;
    int dyn_bytes = 2 * TILE * SMS * sizeof(unsigned);   // 69632 B
    if (smem_set < 0) {
        cudaFuncSetAttribute(pair_mma_kernel,
                             cudaFuncAttributeMaxDynamicSharedMemorySize, dyn_bytes);
        smem_set = 1;
    }

    prep_kernel<<<nblk8, 256>>>(Fi, B, BITS);
    ce_kernel<<<nblk8, 256>>>(Yi, Ym, y, B, C);
    pair_mma_kernel<<<npair, 256, dyn_bytes>>>(Fi, y, B, NT);
    final_kernel<<<1, 1024>>>((float*)d_out, B, BITS, npair, nblk8, nblk8);
}